// round 14
// baseline (speedup 1.0000x reference)
#include <cuda_runtime.h>
#include <cstdint>

#define BATCH    4096
#define FNUM     1024
#define RCNT     19
#define RDIM     1024

#define TPB      (RCNT * 32)          // 608 threads: warp w == relation r
#define ROW      (FNUM * RCNT)        // 19456 floats per batch row
#define CH_F     512                  // f's per chunk (2 chunks per row)
#define CH_FL    (CH_F * RCNT)        // 9728 floats per chunk
#define CH_B     (CH_FL * 4)          // 38912 bytes per chunk
#define NSTAGE   2
#define SMEM_B   (128 + NSTAGE * CH_B)  // 77952 B per CTA -> 2 CTAs/SM

#define FT       4                    // U rows per W-block
#define NFBLK    (FNUM / FT)          // 256 W-blocks

// Precomputed W[f*19 + r] = sum_e U[f,e] * R[r,e]
__device__ float g_W[FNUM * RCNT];

// sense-reversing grid barrier state (persists across graph replays)
__device__ unsigned g_cnt = 0;
__device__ volatile unsigned g_sense = 0;

// ---------------------------------------------------------------------------
// mbarrier parity wait (acquire)
// ---------------------------------------------------------------------------
__device__ __forceinline__ void bar_wait(uint32_t bar, uint32_t parity) {
    uint32_t done;
    asm volatile(
        "{\n\t.reg .pred p;\n\t"
        "mbarrier.try_wait.parity.acquire.cta.shared::cta.b64 p, [%1], %2;\n\t"
        "selp.b32 %0, 1, 0, p;\n\t}"
        : "=r"(done) : "r"(bar), "r"(parity) : "memory");
    if (!done) {
        asm volatile(
            "{\n\t.reg .pred P1;\n\t"
            "WL_%=:\n\t"
            "mbarrier.try_wait.parity.acquire.cta.shared::cta.b64 P1, [%0], %1, 0x989680;\n\t"
            "@P1 bra.uni WD_%=;\n\t"
            "bra.uni WL_%=;\n\t"
            "WD_%=:\n\t}"
            :: "r"(bar), "r"(parity) : "memory");
    }
}

__device__ __forceinline__ void tma_fill(uint32_t bar, uint32_t dst,
                                         const float* src) {
    asm volatile("mbarrier.arrive.expect_tx.shared.b64 _, [%0], %1;"
                 :: "r"(bar), "r"((uint32_t)CH_B) : "memory");
    asm volatile(
        "cp.async.bulk.shared::cta.global.mbarrier::complete_tx::bytes "
        "[%0], [%1], %2, [%3];"
        :: "r"(dst), "l"(src), "r"((uint32_t)CH_B), "r"(bar) : "memory");
}

// ---------------------------------------------------------------------------
// Fused kernel:
//   Phase 1 (overlapped with chunk-0 TMA): W = U @ R^T, warp-per-relation,
//            U block staged in the (currently unused) stage-1 buffer.
//   Grid barrier (sense-reversing, all CTAs resident: grid = 2/SM exactly).
//   Phase 2: streaming scores[b,r] = sum_f conv[b,f,r]*W[f,r], identical to
//            the proven R12 2-stage TMA pipeline.
// ---------------------------------------------------------------------------
__global__ void __launch_bounds__(TPB, 2)
fused_kernel(const float* __restrict__ conv, const float* __restrict__ U,
             const float* __restrict__ R, float* __restrict__ out) {
    extern __shared__ __align__(16) char smem_raw[];
    const uint32_t s_base = (uint32_t)__cvta_generic_to_shared(smem_raw);
    float* bufp = reinterpret_cast<float*>(smem_raw + 128);
    const uint32_t buf_base = s_base + 128;

    const int tid  = threadIdx.x;
    const int lane = tid & 31;
    const int r    = tid >> 5;               // warp id == relation id
    const int G    = gridDim.x;
    const int bid  = blockIdx.x;

    if (tid == 0) {
        asm volatile("mbarrier.init.shared.b64 [%0], 1;" :: "r"(s_base)     : "memory");
        asm volatile("mbarrier.init.shared.b64 [%0], 1;" :: "r"(s_base + 8) : "memory");
    }
    __syncthreads();

    // Kick chunk 0 of this CTA's first row immediately (independent of W).
    if (tid == 0)
        tma_fill(s_base, buf_base, conv + (size_t)bid * ROW);

    // ---------------- Phase 1: W blocks ----------------
    {
        // Warp r's slice of R, held in registers for the whole phase.
        float Rreg[32];
#pragma unroll
        for (int k = 0; k < 32; ++k)
            Rreg[k] = R[(size_t)r * RDIM + lane + 32 * k];

        float*  su  = bufp + CH_FL;          // stage-1 buffer = U staging
        float4* su4 = reinterpret_cast<float4*>(su);

        for (int c = bid; c < NFBLK; c += G) {
            const float4* Ug =
                reinterpret_cast<const float4*>(U + (size_t)c * FT * RDIM);
#pragma unroll 2
            for (int i = tid; i < FT * RDIM / 4; i += TPB)
                su4[i] = Ug[i];
            __syncthreads();

#pragma unroll
            for (int ff = 0; ff < FT; ++ff) {
                float a = 0.f;
#pragma unroll
                for (int k = 0; k < 32; ++k)
                    a = fmaf(su[ff * RDIM + lane + 32 * k], Rreg[k], a);
#pragma unroll
                for (int off = 16; off > 0; off >>= 1)
                    a += __shfl_down_sync(0xffffffffu, a, off);
                if (lane == 0)
                    g_W[(c * FT + ff) * RCNT + r] = a;
            }
            __syncthreads();                 // before su reuse / next block
        }
    }

    // ---------------- grid barrier (sense-reversing) ----------------
    __syncthreads();                          // all CTA warps wrote their W
    if (tid == 0) {
        const unsigned local = g_sense;       // sampled before arriving
        __threadfence();                      // publish this CTA's g_W writes
        const unsigned old = atomicAdd(&g_cnt, 1u);
        if (old == (unsigned)G - 1u) {
            atomicExch(&g_cnt, 0u);           // reset for next replay
            __threadfence();
            atomicExch((unsigned*)&g_sense, local ^ 1u);
        } else {
            while (g_sense == local) __nanosleep(64);
            __threadfence();                  // acquire g_W
        }
    }
    __syncthreads();

    // chunk 1 into stage 1 (U staging no longer needed)
    if (tid == 0)
        tma_fill(s_base + 8, buf_base + CH_B, conv + (size_t)bid * ROW + CH_FL);

    // W values for this (lane, r), reused for every batch row
    float w[32];
#pragma unroll
    for (int k = 0; k < 32; ++k)
        w[k] = g_W[(lane + 32 * k) * RCNT + r];

    // ---------------- Phase 2: streaming (proven R12 loop) ----------------
    int t = 0;
    for (int b = bid; b < BATCH; b += G) {
        float acc = 0.f;
#pragma unroll
        for (int c = 0; c < 2; ++c, ++t) {
            const int s = t & 1;
            bar_wait(s_base + s * 8, (uint32_t)((t >> 1) & 1));

            const float* p = bufp + s * CH_FL + lane * RCNT + r;
#pragma unroll
            for (int k = 0; k < 16; ++k)
                acc = fmaf(p[k * (32 * RCNT)], w[c * 16 + k], acc);

            __syncthreads();                  // all warps done reading stage s

            const int tf = t + NSTAGE;
            const int bf = bid + (tf >> 1) * G;
            if (tid == 0 && bf < BATCH)
                tma_fill(s_base + s * 8, buf_base + s * CH_B,
                         conv + (size_t)bf * ROW + (tf & 1) * CH_FL);
        }

#pragma unroll
        for (int off = 16; off > 0; off >>= 1)
            acc += __shfl_down_sync(0xffffffffu, acc, off);
        if (lane == 0) out[(size_t)b * RCNT + r] = acc;
    }
}

// ---------------------------------------------------------------------------
extern "C" void kernel_launch(void* const* d_in, const int* in_sizes, int n_in,
                              void* d_out, int out_size) {
    const float* conv = nullptr;
    const float* Rm   = nullptr;
    const float* Um   = nullptr;
    for (int i = 0; i < n_in; ++i) {
        if (in_sizes[i] == BATCH * FNUM * RCNT)      conv = (const float*)d_in[i];
        else if (in_sizes[i] == RCNT * RDIM)         Rm   = (const float*)d_in[i];
        else if (in_sizes[i] == FNUM * RDIM)         Um   = (const float*)d_in[i];
    }
    float* out = (float*)d_out;

    static int attr_done = 0;
    if (!attr_done) {
        cudaFuncSetAttribute(fused_kernel,
                             cudaFuncAttributeMaxDynamicSharedMemorySize, SMEM_B);
        attr_done = 1;
    }

    int dev = 0, nsm = 148;
    cudaGetDevice(&dev);
    cudaDeviceGetAttribute(&nsm, cudaDevAttrMultiProcessorCount, dev);

    // grid = exactly-resident persistent set (2 CTAs/SM); required for the
    // device-side grid barrier.
    fused_kernel<<<2 * nsm, TPB, SMEM_B>>>(conv, Um, Rm, out);
}

// round 16
// speedup vs baseline: 1.0362x; 1.0362x over previous
#include <cuda_runtime.h>
#include <cstdint>

#define BATCH    4096
#define FNUM     1024
#define RCNT     19
#define RDIM     1024

#define TPB      (RCNT * 32)          // 608 threads: warp w == relation r
#define ROW      (FNUM * RCNT)        // 19456 floats per batch row
#define CH_F     512                  // f's per chunk (2 chunks per row)
#define CH_FL    (CH_F * RCNT)        // 9728 floats per chunk
#define CH_B     (CH_FL * 4)          // 38912 bytes per chunk
#define NSTAGE   2
#define SMEM_B   (128 + NSTAGE * CH_B)  // 77952 B per CTA -> 2 CTAs/SM

// Precomputed W[f*19 + r] = sum_e U[f,e] * R[r,e]
__device__ float g_W[FNUM * RCNT];

// ---------------------------------------------------------------------------
// Kernel A (primary): W = U @ R^T  (1024 x 19), f-tiled x4.
// Triggers programmatic launch completion immediately so the secondary's
// W-independent prologue overlaps this kernel's whole execution.
// ---------------------------------------------------------------------------
__global__ void __launch_bounds__(256)
compute_w_kernel(const float* __restrict__ U, const float* __restrict__ R) {
    cudaTriggerProgrammaticLaunchCompletion();

    const int f0  = blockIdx.x * 4;
    const int tid = threadIdx.x;
    const float4* U4 = reinterpret_cast<const float4*>(U);
    const float4* R4 = reinterpret_cast<const float4*>(R);

    float4 u[4];
#pragma unroll
    for (int ff = 0; ff < 4; ++ff)
        u[ff] = U4[(size_t)(f0 + ff) * (RDIM / 4) + tid];

    float acc[4][RCNT];
#pragma unroll
    for (int r = 0; r < RCNT; ++r) {
        const float4 rv = R4[(size_t)r * (RDIM / 4) + tid];
#pragma unroll
        for (int ff = 0; ff < 4; ++ff)
            acc[ff][r] = u[ff].x * rv.x + u[ff].y * rv.y
                       + u[ff].z * rv.z + u[ff].w * rv.w;
    }

#pragma unroll
    for (int ff = 0; ff < 4; ++ff)
#pragma unroll
        for (int r = 0; r < RCNT; ++r) {
            float v = acc[ff][r];
#pragma unroll
            for (int off = 16; off > 0; off >>= 1)
                v += __shfl_down_sync(0xffffffffu, v, off);
            acc[ff][r] = v;
        }

    __shared__ float s_red[8][4][RCNT];
    const int warp = tid >> 5, lane = tid & 31;
    if (lane == 0) {
#pragma unroll
        for (int ff = 0; ff < 4; ++ff)
#pragma unroll
            for (int r = 0; r < RCNT; ++r)
                s_red[warp][ff][r] = acc[ff][r];
    }
    __syncthreads();
    if (tid < 4 * RCNT) {
        const int ff = tid / RCNT, r = tid % RCNT;
        float s = 0.f;
#pragma unroll
        for (int w = 0; w < 8; ++w) s += s_red[w][ff][r];
        g_W[(f0 + ff) * RCNT + r] = s;
    }
}

// ---------------------------------------------------------------------------
// mbarrier parity wait (acquire)
// ---------------------------------------------------------------------------
__device__ __forceinline__ void bar_wait(uint32_t bar, uint32_t parity) {
    uint32_t done;
    asm volatile(
        "{\n\t.reg .pred p;\n\t"
        "mbarrier.try_wait.parity.acquire.cta.shared::cta.b64 p, [%1], %2;\n\t"
        "selp.b32 %0, 1, 0, p;\n\t}"
        : "=r"(done) : "r"(bar), "r"(parity) : "memory");
    if (!done) {
        asm volatile(
            "{\n\t.reg .pred P1;\n\t"
            "WL_%=:\n\t"
            "mbarrier.try_wait.parity.acquire.cta.shared::cta.b64 P1, [%0], %1, 0x989680;\n\t"
            "@P1 bra.uni WD_%=;\n\t"
            "bra.uni WL_%=;\n\t"
            "WD_%=:\n\t}"
            :: "r"(bar), "r"(parity) : "memory");
    }
}

__device__ __forceinline__ void tma_fill(uint32_t bar, uint32_t dst,
                                         const float* src) {
    asm volatile("mbarrier.arrive.expect_tx.shared.b64 _, [%0], %1;"
                 :: "r"(bar), "r"((uint32_t)CH_B) : "memory");
    asm volatile(
        "cp.async.bulk.shared::cta.global.mbarrier::complete_tx::bytes "
        "[%0], [%1], %2, [%3];"
        :: "r"(dst), "l"(src), "r"((uint32_t)CH_B), "r"(bar) : "memory");
}

// ---------------------------------------------------------------------------
// Kernel B (secondary, PDL): scores[b,r] = sum_f conv[b,f,r] * W[f,r]
// Launches while compute_w still runs. W-independent prologue (mbarrier
// init + both TMA chunk fills of conv) overlaps the primary; then
// cudaGridDependencySynchronize() guarantees g_W visibility before w-load.
// Streaming loop identical to proven R12 (2-stage TMA, 2 CTAs/SM).
// ---------------------------------------------------------------------------
__global__ void __launch_bounds__(TPB, 2)
score_kernel(const float* __restrict__ conv, float* __restrict__ out) {
    extern __shared__ __align__(16) char smem_raw[];
    const uint32_t s_base = (uint32_t)__cvta_generic_to_shared(smem_raw);
    float* bufp = reinterpret_cast<float*>(smem_raw + 128);
    const uint32_t buf_base = s_base + 128;

    const int tid  = threadIdx.x;
    const int lane = tid & 31;
    const int r    = tid >> 5;               // warp id == relation id
    const int G    = gridDim.x;
    const int bid  = blockIdx.x;

    if (tid == 0) {
        asm volatile("mbarrier.init.shared.b64 [%0], 1;" :: "r"(s_base)     : "memory");
        asm volatile("mbarrier.init.shared.b64 [%0], 1;" :: "r"(s_base + 8) : "memory");
    }
    __syncthreads();

    // W-independent prologue: both halves of this CTA's first row.
    if (tid == 0) {
        tma_fill(s_base,     buf_base,        conv + (size_t)bid * ROW);
        tma_fill(s_base + 8, buf_base + CH_B, conv + (size_t)bid * ROW + CH_FL);
    }

    // Wait for primary kernel (g_W producer) to complete & flush.
    cudaGridDependencySynchronize();

    // W values for this (lane, r), reused for every batch row.
    float w[32];
#pragma unroll
    for (int k = 0; k < 32; ++k)
        w[k] = g_W[(lane + 32 * k) * RCNT + r];

    int t = 0;                                // running chunk counter
    for (int b = bid; b < BATCH; b += G) {
        float acc = 0.f;
#pragma unroll
        for (int c = 0; c < 2; ++c, ++t) {
            const int s = t & 1;
            bar_wait(s_base + s * 8, (uint32_t)((t >> 1) & 1));

            const float* p = bufp + s * CH_FL + lane * RCNT + r;
#pragma unroll
            for (int k = 0; k < 16; ++k)
                acc = fmaf(p[k * (32 * RCNT)], w[c * 16 + k], acc);

            __syncthreads();                  // all warps done reading stage s

            const int tf = t + NSTAGE;
            const int bf = bid + (tf >> 1) * G;
            if (tid == 0 && bf < BATCH)
                tma_fill(s_base + s * 8, buf_base + s * CH_B,
                         conv + (size_t)bf * ROW + (tf & 1) * CH_FL);
        }

#pragma unroll
        for (int off = 16; off > 0; off >>= 1)
            acc += __shfl_down_sync(0xffffffffu, acc, off);
        if (lane == 0) out[(size_t)b * RCNT + r] = acc;
    }
}

// ---------------------------------------------------------------------------
extern "C" void kernel_launch(void* const* d_in, const int* in_sizes, int n_in,
                              void* d_out, int out_size) {
    const float* conv = nullptr;
    const float* Rm   = nullptr;
    const float* Um   = nullptr;
    for (int i = 0; i < n_in; ++i) {
        if (in_sizes[i] == BATCH * FNUM * RCNT)      conv = (const float*)d_in[i];
        else if (in_sizes[i] == RCNT * RDIM)         Rm   = (const float*)d_in[i];
        else if (in_sizes[i] == FNUM * RDIM)         Um   = (const float*)d_in[i];
    }
    float* out = (float*)d_out;

    static int attr_done = 0;
    if (!attr_done) {
        cudaFuncSetAttribute(score_kernel,
                             cudaFuncAttributeMaxDynamicSharedMemorySize, SMEM_B);
        attr_done = 1;
    }

    int dev = 0, nsm = 148;
    cudaGetDevice(&dev);
    cudaDeviceGetAttribute(&nsm, cudaDevAttrMultiProcessorCount, dev);

    // Primary
    compute_w_kernel<<<FNUM / 4, 256>>>(Um, Rm);

    // Secondary with programmatic stream serialization (PDL)
    cudaLaunchConfig_t cfg = {};
    cfg.gridDim         = dim3(2 * nsm, 1, 1);
    cfg.blockDim        = dim3(TPB, 1, 1);
    cfg.dynamicSmemBytes = SMEM_B;
    cfg.stream          = 0;
    cudaLaunchAttribute at[1];
    at[0].id = cudaLaunchAttributeProgrammaticStreamSerialization;
    at[0].val.programmaticStreamSerializationAllowed = 1;
    cfg.attrs    = at;
    cfg.numAttrs = 1;
    cudaLaunchKernelEx(&cfg, score_kernel, conv, out);
}